// round 10
// baseline (speedup 1.0000x reference)
#include <cuda_runtime.h>
#include <cstdint>

#define D     64
#define NREL  32
#define MAXCAT  100000
#define MAXUSER 50000
#define MAXE    1600000
#define MAXNNZ  1000000
#define FULL 0xffffffffu

#define MULX2(o,a,b)   asm("mul.rn.f32x2 %0,%1,%2;"    : "=l"(o) : "l"(a), "l"(b))
#define FMAX2(o,a,b,c) asm("fma.rn.f32x2 %0,%1,%2,%3;" : "=l"(o) : "l"(a), "l"(b), "l"(c))
#define PACK2(o,x)     asm("mov.b64 %0,{%1,%1};"       : "=l"(o) : "f"(x))
#define UNPK2(x,y,i)   asm("mov.b64 {%0,%1},%2;"       : "=f"(x), "=f"(y) : "l"(i))

// ---- scratch ----
__device__ float g_S[(size_t)MAXCAT * NREL];
__device__ int   g_cnt[MAXCAT + MAXUSER + 2];
__device__ int   g_off[MAXCAT + MAXUSER + 2];
__device__ int   g_pos[MAXCAT + MAXUSER + 2];
__device__ int   g_bsum[256];
__device__ int2  g_pk2[MAXE];                     // {tail|rel<<17, att bits}, bucketed by head
__device__ unsigned long long g_up[MAXNNZ];       // col | val<<32, bucketed by user row

// fused: blocks [0,Z) zero the histogram; blocks [Z,Z+SQ) compute S
__global__ void k_front(const float* __restrict__ cat, const float* __restrict__ W,
                        int n_cat, int n_tot, int Z) {
    if ((int)blockIdx.x < Z) {
        int i = blockIdx.x * 256 + threadIdx.x;
        if (i <= n_tot) g_cnt[i] = 0;
        return;
    }
    __shared__ float sw[NREL * D];
    for (int i = threadIdx.x; i < NREL * D; i += blockDim.x) { float v = W[i]; sw[i] = v * v; }
    __syncthreads();
    int c = (blockIdx.x - Z) * 256 + threadIdx.x;
    if (c >= n_cat) return;
    const float4* row = reinterpret_cast<const float4*>(cat + (size_t)c * D);
    float c2[D];
#pragma unroll
    for (int i = 0; i < D / 4; i++) {
        float4 v = row[i];
        c2[4*i+0] = v.x*v.x; c2[4*i+1] = v.y*v.y; c2[4*i+2] = v.z*v.z; c2[4*i+3] = v.w*v.w;
    }
    float* out = g_S + (size_t)c * NREL;
#pragma unroll 4
    for (int r = 0; r < NREL; r++) {
        const float4* w4 = reinterpret_cast<const float4*>(sw + r * D);
        float acc = 0.f;
#pragma unroll
        for (int i = 0; i < D / 4; i++) {
            float4 w = w4[i];
            acc += c2[4*i+0]*w.x + c2[4*i+1]*w.y + c2[4*i+2]*w.z + c2[4*i+3]*w.w;
        }
        out[r] = acc;
    }
}

__global__ void k_hist(const int* __restrict__ head, const int* __restrict__ irow,
                       int E, int nnz, int n_cat) {
    int i = blockIdx.x * blockDim.x + threadIdx.x;
    if (i < E) atomicAdd(&g_cnt[head[i]], 1);
    else { int j = i - E; if (j < nnz) atomicAdd(&g_cnt[n_cat + irow[j]], 1); }
}

__global__ void k_scanA(int n) {
    __shared__ int s[1024];
    int tid = threadIdx.x;
    int i = blockIdx.x * 1024 + tid;
    int v = (i < n) ? g_cnt[i] : 0;
    s[tid] = v; __syncthreads();
    for (int o = 1; o < 1024; o <<= 1) {
        int t = (tid >= o) ? s[tid - o] : 0;
        __syncthreads();
        s[tid] += t;
        __syncthreads();
    }
    if (i < n) g_off[i] = s[tid] - v;
    if (tid == 1023) g_bsum[blockIdx.x] = s[1023];
}

__global__ void k_scanB(int nb, int n) {
    __shared__ int s[256];
    int tid = threadIdx.x;
    int v = (tid < nb) ? g_bsum[tid] : 0;
    s[tid] = v; __syncthreads();
    for (int o = 1; o < 256; o <<= 1) {
        int t = (tid >= o) ? s[tid - o] : 0;
        __syncthreads();
        s[tid] += t;
        __syncthreads();
    }
    if (tid < nb) g_bsum[tid] = s[tid] - v;
    if (tid == 255) g_off[n] = s[255];
}

__global__ void k_scanC(int n) {
    int i = blockIdx.x * 1024 + threadIdx.x;
    if (i < n) {
        int o = g_off[i] + g_bsum[blockIdx.x];
        g_off[i] = o;
        g_pos[i] = o;
    }
}

// bucket-scatter; edge side also precomputes att = S[h,r]*S[t,r]
__global__ void k_sort(const int* __restrict__ head, const int* __restrict__ tail,
                       const int* __restrict__ et,
                       const int* __restrict__ irow, const int* __restrict__ icol,
                       const float* __restrict__ ival, int E, int nnz, int n_cat) {
    int i = blockIdx.x * blockDim.x + threadIdx.x;
    if (i < E) {
        int h = head[i], t = tail[i], r = et[i] - 1;
        float att = g_S[(size_t)h * NREL + r] * g_S[(size_t)t * NREL + r];
        int p = atomicAdd(&g_pos[h], 1);
        g_pk2[p] = make_int2(t | (r << 17), __float_as_int(att));
    } else {
        int j = i - E;
        if (j < nnz) {
            int r = irow[j];
            int p = atomicAdd(&g_pos[n_cat + r], 1) - E;
            g_up[p] = (unsigned int)icol[j] |
                      ((unsigned long long)__float_as_uint(ival[j]) << 32);
        }
    }
}

// persistent fused kernel with cross-iteration prefetch pipelining.
__global__ void __launch_bounds__(256, 6) k_big(const float* __restrict__ cat,
                                                const float* __restrict__ ue,
                                                const float* __restrict__ W,
                                                float* __restrict__ agg,
                                                float* __restrict__ ua,
                                                int n_cat, int n_users, int E, int GA) {
    __shared__ __align__(16) float sw[NREL * D];     // W row-major
    __shared__ float swT[D * NREL];                  // swT[d*32+r] = W[r,d] (user side)
    int warp = threadIdx.x >> 5, lane = threadIdx.x & 31;
    int half = lane >> 4;
    int l16  = lane & 15;

    if ((int)blockIdx.x < GA) {
        // ---------------- head aggregation (online softmax, pipelined) ----------------
        for (int i = threadIdx.x; i < NREL * D; i += blockDim.x) sw[i] = W[i];
        __syncthreads();
        int strideH = GA * 8;
        int h = blockIdx.x * 8 + warp;
        int beg = 0, end = 0;
        int2 pa0 = make_int2(0, 0);
        if (h < n_cat) {
            beg = g_off[h]; end = g_off[h + 1];
            if (beg + lane < end) pa0 = g_pk2[beg + lane];
        }
        while (h < n_cat) {
            // prefetch next head's offsets + first edge batch (overlaps current work)
            int hn = h + strideH;
            int nbeg = 0, nend = 0;
            int2 npa = make_int2(0, 0);
            if (hn < n_cat) {
                nbeg = g_off[hn]; nend = g_off[hn + 1];
                if (nbeg + lane < nend) npa = g_pk2[nbeg + lane];
            }

            float4* dst4 = reinterpret_cast<float4*>(agg + (size_t)h * D);
            if (beg == end) {
                if (lane < 16) dst4[lane] = make_float4(0.f, 0.f, 0.f, 0.f);
            } else {
                float m = 0.f, sum = 0.f;
                unsigned long long a01 = 0ull, a23 = 0ull;
                for (int b = beg; b < end; b += 32) {
                    int i2 = b + lane;
                    bool val = i2 < end;
                    int2 pa = (b == beg) ? pa0
                              : (val ? g_pk2[i2] : make_int2(0, 0));
                    float a = val ? __int_as_float(pa.y) : 0.f;
                    int mi;
                    asm("redux.sync.max.s32 %0, %1, 0xffffffff;" : "=r"(mi) : "r"(__float_as_int(a)));
                    float bm = __int_as_float(mi);
                    if (b == beg) {
                        m = bm;
                    } else {
                        float mnew = fmaxf(m, bm);
                        float scale = __expf(m - mnew);
                        m = mnew;
                        sum *= scale;
                        unsigned long long sc2;
                        PACK2(sc2, scale);
                        MULX2(a01, a01, sc2);
                        MULX2(a23, a23, sc2);
                    }
                    float e = val ? __expf(a - m) : 0.f;
                    float cs = e;
#pragma unroll
                    for (int o = 16; o > 0; o >>= 1) cs += __shfl_xor_sync(FULL, cs, o);
                    sum += cs;
                    int cnt = min(32, end - b);
                    int cntUp = (cnt + 7) & ~7;        // pads have e=0, pk=0 -> harmless
                    for (int j = 0; j < cntUp; j += 8) {
#pragma unroll
                        for (int q = 0; q < 8; q += 2) {
                            int src = j + q + half;
                            float ej = __shfl_sync(FULL, e, src);
                            int pj = __shfl_sync(FULL, pa.x, src);
                            int tj = pj & 0x1FFFF, rj = pj >> 17;
                            ulonglong2 cv = reinterpret_cast<const ulonglong2*>(cat + (size_t)tj * D)[l16];
                            ulonglong2 wv = reinterpret_cast<const ulonglong2*>(sw + rj * D)[l16];
                            unsigned long long ee, t1;
                            PACK2(ee, ej);
                            MULX2(t1, cv.x, wv.x); FMAX2(a01, t1, ee, a01);
                            MULX2(t1, cv.y, wv.y); FMAX2(a23, t1, ee, a23);
                        }
                    }
                }
                float x0, x1, x2, x3;
                UNPK2(x0, x1, a01);
                UNPK2(x2, x3, a23);
                x0 += __shfl_xor_sync(FULL, x0, 16);
                x1 += __shfl_xor_sync(FULL, x1, 16);
                x2 += __shfl_xor_sync(FULL, x2, 16);
                x3 += __shfl_xor_sync(FULL, x3, 16);
                float inv = 1.f / sum;
                if (lane < 16)
                    dst4[lane] = make_float4(x0 * inv, x1 * inv, x2 * inv, x3 * inv);
            }
            h = hn; beg = nbeg; end = nend; pa0 = npa;
        }
    } else {
        // ---------------- user rows + gating (pipelined) ----------------
        for (int i = threadIdx.x; i < NREL * D; i += blockDim.x) {
            float v = W[i];
            sw[i] = v;
            int r = i / D, d = i % D;
            swT[d * NREL + r] = v;
        }
        __syncthreads();
        int GB = gridDim.x - GA;
        int strideU = GB * 8;
        int u = (blockIdx.x - GA) * 8 + warp;
        int beg = 0, end = 0;
        unsigned long long up0 = 0ull;
        if (u < n_users) {
            beg = g_off[n_cat + u] - E; end = g_off[n_cat + u + 1] - E;
            if (beg + lane < end) up0 = g_up[beg + lane];
        }
        while (u < n_users) {
            int un = u + strideU;
            int nbeg = 0, nend = 0;
            unsigned long long nup = 0ull;
            if (un < n_users) {
                nbeg = g_off[n_cat + un] - E; nend = g_off[n_cat + un + 1] - E;
                if (nbeg + lane < nend) nup = g_up[nbeg + lane];
            }
            // gating inputs issued early (coalesced; overlap accumulation)
            float u0 = ue[(size_t)u * D + lane];
            float u1 = ue[(size_t)u * D + 32 + lane];

            unsigned long long a01 = 0ull, a23 = 0ull;
            for (int b = beg; b < end; b += 32) {
                int i2 = b + lane;
                bool val = i2 < end;
                unsigned long long cvp = (b == beg) ? up0 : (val ? g_up[i2] : 0ull);
                int c = (int)(unsigned int)cvp;
                float v = val ? __uint_as_float((unsigned int)(cvp >> 32)) : 0.f;
                int cnt = min(32, end - b);
                int cntUp = (cnt + 7) & ~7;
                for (int j = 0; j < cntUp; j += 8) {
#pragma unroll
                    for (int q = 0; q < 8; q += 2) {
                        int src = j + q + half;
                        int cj = __shfl_sync(FULL, c, src);
                        float vj = __shfl_sync(FULL, v, src);
                        ulonglong2 cv = reinterpret_cast<const ulonglong2*>(cat + (size_t)cj * D)[l16];
                        unsigned long long vv;
                        PACK2(vv, vj);
                        FMAX2(a01, cv.x, vv, a01);
                        FMAX2(a23, cv.y, vv, a23);
                    }
                }
            }
            float x0, x1, x2, x3;
            UNPK2(x0, x1, a01);
            UNPK2(x2, x3, a23);
            x0 += __shfl_xor_sync(FULL, x0, 16);
            x1 += __shfl_xor_sync(FULL, x1, 16);
            x2 += __shfl_xor_sync(FULL, x2, 16);
            x3 += __shfl_xor_sync(FULL, x3, 16);
            float v0 = __shfl_sync(FULL, x0, lane >> 1);
            float v1 = __shfl_sync(FULL, x1, lane >> 1);
            float v2 = __shfl_sync(FULL, x2, lane >> 1);
            float v3 = __shfl_sync(FULL, x3, lane >> 1);
            float ax = (lane & 1) ? v2 : v0;
            float ay = (lane & 1) ? v3 : v1;
            float logit = 0.f;
#pragma unroll
            for (int d = 0; d < 32; d++) {
                float ud = __shfl_sync(FULL, u0, d);
                logit += ud * swT[d * NREL + lane];
            }
#pragma unroll
            for (int d = 0; d < 32; d++) {
                float ud = __shfl_sync(FULL, u1, d);
                logit += ud * swT[(d + 32) * NREL + lane];
            }
            float mm = logit;
#pragma unroll
            for (int o = 16; o > 0; o >>= 1) mm = fmaxf(mm, __shfl_xor_sync(FULL, mm, o));
            float p = __expf(logit - mm);
            float s = p;
#pragma unroll
            for (int o = 16; o > 0; o >>= 1) s += __shfl_xor_sync(FULL, s, o);
            p /= s;
            float cx = 0.f, cy = 0.f;
#pragma unroll
            for (int r = 0; r < NREL; r++) {
                float pr = __shfl_sync(FULL, p, r);
                float2 w2 = reinterpret_cast<const float2*>(sw + r * D)[lane];
                cx += pr * w2.x;
                cy += pr * w2.y;
            }
            float2* ud2 = reinterpret_cast<float2*>(ua + (size_t)u * D);
            ud2[lane] = make_float2(ax * (1.f + cx), ay * (1.f + cy));

            u = un; beg = nbeg; end = nend; up0 = nup;
        }
    }
}

extern "C" void kernel_launch(void* const* d_in, const int* in_sizes, int n_in,
                              void* d_out, int out_size) {
    const float* cat = (const float*)d_in[0];
    const float* ue  = (const float*)d_in[1];
    const int*   ei  = (const int*)d_in[2];
    const int*   et  = (const int*)d_in[3];
    const int*   ir  = (const int*)d_in[4];
    const int*   ic  = (const int*)d_in[5];
    const float* iv  = (const float*)d_in[6];
    const float* W   = (const float*)d_in[7];

    int n_cat   = in_sizes[0] / D;
    int n_users = in_sizes[1] / D;
    int E       = in_sizes[3];
    int nnz     = in_sizes[6];

    const int* head = ei;
    const int* tail = ei + E;

    float* cat_agg  = (float*)d_out;
    float* user_agg = (float*)d_out + (size_t)n_cat * D;

    int n_tot = n_cat + n_users;
    int tot   = E + nnz;
    int nb    = (n_tot + 1023) / 1024;
    int Z     = (n_tot + 256) / 256;
    int SQ    = (n_cat + 255) / 256;

    const int GA = 612, GB = 276;   // GA+GB = 888 = 148 SMs * 6 blocks

    k_front<<<Z + SQ, 256>>>(cat, W, n_cat, n_tot, Z);
    k_hist<<<(tot + 255) / 256, 256>>>(head, ir, E, nnz, n_cat);
    k_scanA<<<nb, 1024>>>(n_tot);
    k_scanB<<<1, 256>>>(nb, n_tot);
    k_scanC<<<nb, 1024>>>(n_tot);
    k_sort<<<(tot + 255) / 256, 256>>>(head, tail, et, ir, ic, iv, E, nnz, n_cat);
    k_big<<<GA + GB, 256>>>(cat, ue, W, cat_agg, user_agg, n_cat, n_users, E, GA);
}

// round 12
// speedup vs baseline: 1.1008x; 1.1008x over previous
#include <cuda_runtime.h>
#include <cstdint>

#define D     64
#define NREL  32
#define MAXCAT  100000
#define MAXUSER 50000
#define MAXE    1600000
#define MAXNNZ  1000000
#define FULL 0xffffffffu

#define MULX2(o,a,b)   asm("mul.rn.f32x2 %0,%1,%2;"    : "=l"(o) : "l"(a), "l"(b))
#define FMAX2(o,a,b,c) asm("fma.rn.f32x2 %0,%1,%2,%3;" : "=l"(o) : "l"(a), "l"(b), "l"(c))
#define PACK2(o,x)     asm("mov.b64 %0,{%1,%1};"       : "=l"(o) : "f"(x))
#define UNPK2(x,y,i)   asm("mov.b64 {%0,%1},%2;"       : "=f"(x), "=f"(y) : "l"(i))

// ---- scratch (g_cnt: static zero-init; k_big re-zeroes it at the end of every run) ----
__device__ float g_S[(size_t)MAXCAT * NREL];
__device__ int   g_cnt[MAXCAT + MAXUSER + 2];
__device__ int   g_off[MAXCAT + MAXUSER + 2];
__device__ int   g_pos[MAXCAT + MAXUSER + 2];
__device__ int   g_bsum[256];
__device__ int2  g_pk2[MAXE];                     // {tail|rel<<17, att bits}, bucketed by head
__device__ unsigned long long g_up[MAXNNZ];       // col | val<<32, bucketed by user row

// fused: blocks [0,H) histogram heads/user-rows; blocks [H,H+SQ) compute S
__global__ void k_front(const float* __restrict__ cat, const float* __restrict__ W,
                        const int* __restrict__ head, const int* __restrict__ irow,
                        int n_cat, int E, int nnz, int H) {
    if ((int)blockIdx.x < H) {
        int i = blockIdx.x * 256 + threadIdx.x;
        if (i < E) atomicAdd(&g_cnt[head[i]], 1);
        else { int j = i - E; if (j < nnz) atomicAdd(&g_cnt[n_cat + irow[j]], 1); }
        return;
    }
    __shared__ float sw[NREL * D];
    for (int i = threadIdx.x; i < NREL * D; i += blockDim.x) { float v = W[i]; sw[i] = v * v; }
    __syncthreads();
    int c = (blockIdx.x - H) * 256 + threadIdx.x;
    if (c >= n_cat) return;
    const float4* row = reinterpret_cast<const float4*>(cat + (size_t)c * D);
    float c2[D];
#pragma unroll
    for (int i = 0; i < D / 4; i++) {
        float4 v = row[i];
        c2[4*i+0] = v.x*v.x; c2[4*i+1] = v.y*v.y; c2[4*i+2] = v.z*v.z; c2[4*i+3] = v.w*v.w;
    }
    float* out = g_S + (size_t)c * NREL;
#pragma unroll 4
    for (int r = 0; r < NREL; r++) {
        const float4* w4 = reinterpret_cast<const float4*>(sw + r * D);
        float acc = 0.f;
#pragma unroll
        for (int i = 0; i < D / 4; i++) {
            float4 w = w4[i];
            acc += c2[4*i+0]*w.x + c2[4*i+1]*w.y + c2[4*i+2]*w.z + c2[4*i+3]*w.w;
        }
        out[r] = acc;
    }
}

__global__ void k_scanA(int n) {
    __shared__ int s[1024];
    int tid = threadIdx.x;
    int i = blockIdx.x * 1024 + tid;
    int v = (i < n) ? g_cnt[i] : 0;
    s[tid] = v; __syncthreads();
    for (int o = 1; o < 1024; o <<= 1) {
        int t = (tid >= o) ? s[tid - o] : 0;
        __syncthreads();
        s[tid] += t;
        __syncthreads();
    }
    if (i < n) g_off[i] = s[tid] - v;
    if (tid == 1023) g_bsum[blockIdx.x] = s[1023];
}

__global__ void k_scanB(int nb, int n) {
    __shared__ int s[256];
    int tid = threadIdx.x;
    int v = (tid < nb) ? g_bsum[tid] : 0;
    s[tid] = v; __syncthreads();
    for (int o = 1; o < 256; o <<= 1) {
        int t = (tid >= o) ? s[tid - o] : 0;
        __syncthreads();
        s[tid] += t;
        __syncthreads();
    }
    if (tid < nb) g_bsum[tid] = s[tid] - v;
    if (tid == 255) g_off[n] = s[255];
}

__global__ void k_scanC(int n) {
    int i = blockIdx.x * 1024 + threadIdx.x;
    if (i < n) {
        int o = g_off[i] + g_bsum[blockIdx.x];
        g_off[i] = o;
        g_pos[i] = o;
    }
}

// bucket-scatter; edge side also precomputes att = S[h,r]*S[t,r]
__global__ void k_sort(const int* __restrict__ head, const int* __restrict__ tail,
                       const int* __restrict__ et,
                       const int* __restrict__ irow, const int* __restrict__ icol,
                       const float* __restrict__ ival, int E, int nnz, int n_cat) {
    int i = blockIdx.x * blockDim.x + threadIdx.x;
    if (i < E) {
        int h = head[i], t = tail[i], r = et[i] - 1;
        float att = g_S[(size_t)h * NREL + r] * g_S[(size_t)t * NREL + r];
        int p = atomicAdd(&g_pos[h], 1);
        g_pk2[p] = make_int2(t | (r << 17), __float_as_int(att));
    } else {
        int j = i - E;
        if (j < nnz) {
            int r = irow[j];
            int p = atomicAdd(&g_pos[n_cat + r], 1) - E;
            g_up[p] = (unsigned int)icol[j] |
                      ((unsigned long long)__float_as_uint(ival[j]) << 32);
        }
    }
}

// persistent fused kernel: blocks [0,GA) heads (online softmax agg); rest users.
// Tail: re-zero g_cnt for the next invocation (self-cleaning).
__global__ void __launch_bounds__(256, 6) k_big(const float* __restrict__ cat,
                                                const float* __restrict__ ue,
                                                const float* __restrict__ W,
                                                float* __restrict__ agg,
                                                float* __restrict__ ua,
                                                int n_cat, int n_users, int E, int GA) {
    __shared__ __align__(16) float sw[NREL * D];     // W row-major
    __shared__ float swT[D * NREL];                  // swT[d*32+r] = W[r,d] (user side)
    int warp = threadIdx.x >> 5, lane = threadIdx.x & 31;
    int half = lane >> 4;
    int l16  = lane & 15;

    if ((int)blockIdx.x < GA) {
        // ---------------- head aggregation (online softmax) ----------------
        for (int i = threadIdx.x; i < NREL * D; i += blockDim.x) sw[i] = W[i];
        __syncthreads();
        int strideH = GA * 8;
        for (int h = blockIdx.x * 8 + warp; h < n_cat; h += strideH) {
            int beg = g_off[h], end = g_off[h + 1];
            float4* dst4 = reinterpret_cast<float4*>(agg + (size_t)h * D);
            if (beg == end) {
                if (lane < 16) dst4[lane] = make_float4(0.f, 0.f, 0.f, 0.f);
                continue;
            }
            float m = 0.f, sum = 0.f;                  // att >= 0
            unsigned long long a01 = 0ull, a23 = 0ull;
            for (int b = beg; b < end; b += 32) {
                int i2 = b + lane;
                bool val = i2 < end;
                int2 pa = val ? g_pk2[i2] : make_int2(0, 0);
                float a = val ? __int_as_float(pa.y) : 0.f;
                int mi;
                asm("redux.sync.max.s32 %0, %1, 0xffffffff;" : "=r"(mi) : "r"(__float_as_int(a)));
                float bm = __int_as_float(mi);
                if (b == beg) {
                    m = bm;                            // accs are zero: no rescale needed
                } else {
                    float mnew = fmaxf(m, bm);
                    float scale = __expf(m - mnew);
                    m = mnew;
                    sum *= scale;
                    unsigned long long sc2;
                    PACK2(sc2, scale);
                    MULX2(a01, a01, sc2);
                    MULX2(a23, a23, sc2);
                }
                float e = val ? __expf(a - m) : 0.f;
                float cs = e;
#pragma unroll
                for (int o = 16; o > 0; o >>= 1) cs += __shfl_xor_sync(FULL, cs, o);
                sum += cs;
                int cnt = min(32, end - b);
                int cntUp = (cnt + 7) & ~7;            // pads have e=0, pk=0 -> harmless
                for (int j = 0; j < cntUp; j += 8) {
#pragma unroll
                    for (int q = 0; q < 8; q += 2) {
                        int src = j + q + half;
                        float ej = __shfl_sync(FULL, e, src);
                        int pj = __shfl_sync(FULL, pa.x, src);
                        int tj = pj & 0x1FFFF, rj = pj >> 17;
                        ulonglong2 cv = reinterpret_cast<const ulonglong2*>(cat + (size_t)tj * D)[l16];
                        ulonglong2 wv = reinterpret_cast<const ulonglong2*>(sw + rj * D)[l16];
                        unsigned long long ee, t1;
                        PACK2(ee, ej);
                        MULX2(t1, cv.x, wv.x); FMAX2(a01, t1, ee, a01);
                        MULX2(t1, cv.y, wv.y); FMAX2(a23, t1, ee, a23);
                    }
                }
            }
            float x0, x1, x2, x3;
            UNPK2(x0, x1, a01);
            UNPK2(x2, x3, a23);
            x0 += __shfl_xor_sync(FULL, x0, 16);
            x1 += __shfl_xor_sync(FULL, x1, 16);
            x2 += __shfl_xor_sync(FULL, x2, 16);
            x3 += __shfl_xor_sync(FULL, x3, 16);
            float inv = 1.f / sum;
            if (lane < 16)
                dst4[lane] = make_float4(x0 * inv, x1 * inv, x2 * inv, x3 * inv);
        }
    } else {
        // ---------------- user rows + gating ----------------
        for (int i = threadIdx.x; i < NREL * D; i += blockDim.x) {
            float v = W[i];
            sw[i] = v;
            int r = i / D, d = i % D;
            swT[d * NREL + r] = v;
        }
        __syncthreads();
        int GB = gridDim.x - GA;
        int strideU = GB * 8;
        for (int u = (blockIdx.x - GA) * 8 + warp; u < n_users; u += strideU) {
            int beg = g_off[n_cat + u] - E, end = g_off[n_cat + u + 1] - E;
            unsigned long long a01 = 0ull, a23 = 0ull;
            for (int b = beg; b < end; b += 32) {
                int i2 = b + lane;
                bool val = i2 < end;
                unsigned long long cvp = val ? g_up[i2] : 0ull;
                int c = (int)(unsigned int)cvp;
                float v = val ? __uint_as_float((unsigned int)(cvp >> 32)) : 0.f;
                int cnt = min(32, end - b);
                int cntUp = (cnt + 7) & ~7;
                for (int j = 0; j < cntUp; j += 8) {
#pragma unroll
                    for (int q = 0; q < 8; q += 2) {
                        int src = j + q + half;
                        int cj = __shfl_sync(FULL, c, src);
                        float vj = __shfl_sync(FULL, v, src);
                        ulonglong2 cv = reinterpret_cast<const ulonglong2*>(cat + (size_t)cj * D)[l16];
                        unsigned long long vv;
                        PACK2(vv, vj);
                        FMAX2(a01, cv.x, vv, a01);
                        FMAX2(a23, cv.y, vv, a23);
                    }
                }
            }
            float x0, x1, x2, x3;
            UNPK2(x0, x1, a01);
            UNPK2(x2, x3, a23);
            x0 += __shfl_xor_sync(FULL, x0, 16);
            x1 += __shfl_xor_sync(FULL, x1, 16);
            x2 += __shfl_xor_sync(FULL, x2, 16);
            x3 += __shfl_xor_sync(FULL, x3, 16);
            // redistribute float4@lane<16 -> float2 per lane
            float v0 = __shfl_sync(FULL, x0, lane >> 1);
            float v1 = __shfl_sync(FULL, x1, lane >> 1);
            float v2 = __shfl_sync(FULL, x2, lane >> 1);
            float v3 = __shfl_sync(FULL, x3, lane >> 1);
            float ax = (lane & 1) ? v2 : v0;
            float ay = (lane & 1) ? v3 : v1;
            // gating: score = softmax(ue[u] @ W^T); out = acc * (1 + score @ W)
            float u0 = ue[(size_t)u * D + lane];
            float u1 = ue[(size_t)u * D + 32 + lane];
            float logit = 0.f;
#pragma unroll
            for (int d = 0; d < 32; d++) {
                float ud = __shfl_sync(FULL, u0, d);
                logit += ud * swT[d * NREL + lane];
            }
#pragma unroll
            for (int d = 0; d < 32; d++) {
                float ud = __shfl_sync(FULL, u1, d);
                logit += ud * swT[(d + 32) * NREL + lane];
            }
            float mm = logit;
#pragma unroll
            for (int o = 16; o > 0; o >>= 1) mm = fmaxf(mm, __shfl_xor_sync(FULL, mm, o));
            float p = __expf(logit - mm);
            float s = p;
#pragma unroll
            for (int o = 16; o > 0; o >>= 1) s += __shfl_xor_sync(FULL, s, o);
            p /= s;
            float cx = 0.f, cy = 0.f;
#pragma unroll
            for (int r = 0; r < NREL; r++) {
                float pr = __shfl_sync(FULL, p, r);
                float2 w2 = reinterpret_cast<const float2*>(sw + r * D)[lane];
                cx += pr * w2.x;
                cy += pr * w2.y;
            }
            float2* ud2 = reinterpret_cast<float2*>(ua + (size_t)u * D);
            ud2[lane] = make_float2(ax * (1.f + cx), ay * (1.f + cy));
        }
    }
    // self-clean: leave g_cnt zeroed for the next invocation
    int n_tot = n_cat + n_users;
    for (int i = blockIdx.x * 256 + threadIdx.x; i <= n_tot; i += gridDim.x * 256)
        g_cnt[i] = 0;
}

extern "C" void kernel_launch(void* const* d_in, const int* in_sizes, int n_in,
                              void* d_out, int out_size) {
    const float* cat = (const float*)d_in[0];
    const float* ue  = (const float*)d_in[1];
    const int*   ei  = (const int*)d_in[2];
    const int*   et  = (const int*)d_in[3];
    const int*   ir  = (const int*)d_in[4];
    const int*   ic  = (const int*)d_in[5];
    const float* iv  = (const float*)d_in[6];
    const float* W   = (const float*)d_in[7];

    int n_cat   = in_sizes[0] / D;
    int n_users = in_sizes[1] / D;
    int E       = in_sizes[3];
    int nnz     = in_sizes[6];

    const int* head = ei;
    const int* tail = ei + E;

    float* cat_agg  = (float*)d_out;
    float* user_agg = (float*)d_out + (size_t)n_cat * D;

    int n_tot = n_cat + n_users;
    int tot   = E + nnz;
    int nb    = (n_tot + 1023) / 1024;
    int H     = (tot + 255) / 256;
    int SQ    = (n_cat + 255) / 256;

    const int GA = 612, GB = 276;   // GA+GB = 888 = 148 SMs * 6 blocks

    k_front<<<H + SQ, 256>>>(cat, W, head, ir, n_cat, E, nnz, H);
    k_scanA<<<nb, 1024>>>(n_tot);
    k_scanB<<<1, 256>>>(nb, n_tot);
    k_scanC<<<nb, 1024>>>(n_tot);
    k_sort<<<(tot + 255) / 256, 256>>>(head, tail, et, ir, ic, iv, E, nnz, n_cat);
    k_big<<<GA + GB, 256>>>(cat, ue, W, cat_agg, user_agg, n_cat, n_users, E, GA);
}

// round 13
// speedup vs baseline: 1.1288x; 1.0255x over previous
#include <cuda_runtime.h>
#include <cstdint>

#define D     64
#define NREL  32
#define MAXCAT  100000
#define MAXUSER 50000
#define MAXE    1600000
#define MAXNNZ  1000000
#define FULL 0xffffffffu

#define MULX2(o,a,b)   asm("mul.rn.f32x2 %0,%1,%2;"    : "=l"(o) : "l"(a), "l"(b))
#define FMAX2(o,a,b,c) asm("fma.rn.f32x2 %0,%1,%2,%3;" : "=l"(o) : "l"(a), "l"(b), "l"(c))
#define PACK2(o,x)     asm("mov.b64 %0,{%1,%1};"       : "=l"(o) : "f"(x))
#define UNPK2(x,y,i)   asm("mov.b64 {%0,%1},%2;"       : "=f"(x), "=f"(y) : "l"(i))

// ---- scratch ----
__device__ float g_S[(size_t)MAXCAT * NREL];
__device__ int   g_cnt[MAXCAT + MAXUSER + 2];
__device__ int   g_off[MAXCAT + MAXUSER + 2];
__device__ int   g_pos[MAXCAT + MAXUSER + 2];
__device__ int   g_bsum[256];
__device__ int2  g_pk2[MAXE];                     // {tail|rel<<17, att bits}, bucketed by head
__device__ unsigned long long g_up[MAXNNZ];       // col | val<<32, bucketed by user row

// fused: blocks [0,Z) zero the histogram; blocks [Z,Z+SQ) compute S
__global__ void k_front(const float* __restrict__ cat, const float* __restrict__ W,
                        int n_cat, int n_tot, int Z) {
    if ((int)blockIdx.x < Z) {
        int i = blockIdx.x * 256 + threadIdx.x;
        if (i <= n_tot) g_cnt[i] = 0;
        return;
    }
    __shared__ float sw[NREL * D];
    for (int i = threadIdx.x; i < NREL * D; i += blockDim.x) { float v = W[i]; sw[i] = v * v; }
    __syncthreads();
    int c = (blockIdx.x - Z) * 256 + threadIdx.x;
    if (c >= n_cat) return;
    const float4* row = reinterpret_cast<const float4*>(cat + (size_t)c * D);
    float c2[D];
#pragma unroll
    for (int i = 0; i < D / 4; i++) {
        float4 v = row[i];
        c2[4*i+0] = v.x*v.x; c2[4*i+1] = v.y*v.y; c2[4*i+2] = v.z*v.z; c2[4*i+3] = v.w*v.w;
    }
    float* out = g_S + (size_t)c * NREL;
#pragma unroll 4
    for (int r = 0; r < NREL; r++) {
        const float4* w4 = reinterpret_cast<const float4*>(sw + r * D);
        float acc = 0.f;
#pragma unroll
        for (int i = 0; i < D / 4; i++) {
            float4 w = w4[i];
            acc += c2[4*i+0]*w.x + c2[4*i+1]*w.y + c2[4*i+2]*w.z + c2[4*i+3]*w.w;
        }
        out[r] = acc;
    }
}

__global__ void k_hist(const int* __restrict__ head, const int* __restrict__ irow,
                       int E, int nnz, int n_cat) {
    int i = blockIdx.x * blockDim.x + threadIdx.x;
    if (i < E) atomicAdd(&g_cnt[head[i]], 1);
    else { int j = i - E; if (j < nnz) atomicAdd(&g_cnt[n_cat + irow[j]], 1); }
}

__global__ void k_scanA(int n) {
    __shared__ int s[1024];
    int tid = threadIdx.x;
    int i = blockIdx.x * 1024 + tid;
    int v = (i < n) ? g_cnt[i] : 0;
    s[tid] = v; __syncthreads();
    for (int o = 1; o < 1024; o <<= 1) {
        int t = (tid >= o) ? s[tid - o] : 0;
        __syncthreads();
        s[tid] += t;
        __syncthreads();
    }
    if (i < n) g_off[i] = s[tid] - v;
    if (tid == 1023) g_bsum[blockIdx.x] = s[1023];
}

__global__ void k_scanB(int nb, int n) {
    __shared__ int s[256];
    int tid = threadIdx.x;
    int v = (tid < nb) ? g_bsum[tid] : 0;
    s[tid] = v; __syncthreads();
    for (int o = 1; o < 256; o <<= 1) {
        int t = (tid >= o) ? s[tid - o] : 0;
        __syncthreads();
        s[tid] += t;
        __syncthreads();
    }
    if (tid < nb) g_bsum[tid] = s[tid] - v;
    if (tid == 255) g_off[n] = s[255];
}

__global__ void k_scanC(int n) {
    int i = blockIdx.x * 1024 + threadIdx.x;
    if (i < n) {
        int o = g_off[i] + g_bsum[blockIdx.x];
        g_off[i] = o;
        g_pos[i] = o;
    }
}

// bucket-scatter; edge side also precomputes att = S[h,r]*S[t,r]
__global__ void k_sort(const int* __restrict__ head, const int* __restrict__ tail,
                       const int* __restrict__ et,
                       const int* __restrict__ irow, const int* __restrict__ icol,
                       const float* __restrict__ ival, int E, int nnz, int n_cat) {
    int i = blockIdx.x * blockDim.x + threadIdx.x;
    if (i < E) {
        int h = head[i], t = tail[i], r = et[i] - 1;
        float att = g_S[(size_t)h * NREL + r] * g_S[(size_t)t * NREL + r];
        int p = atomicAdd(&g_pos[h], 1);
        g_pk2[p] = make_int2(t | (r << 17), __float_as_int(att));
    } else {
        int j = i - E;
        if (j < nnz) {
            int r = irow[j];
            int p = atomicAdd(&g_pos[n_cat + r], 1) - E;
            g_up[p] = (unsigned int)icol[j] |
                      ((unsigned long long)__float_as_uint(ival[j]) << 32);
        }
    }
}

// persistent fused kernel: blocks [0,GA) heads (online softmax agg); rest users.
__global__ void __launch_bounds__(256, 6) k_big(const float* __restrict__ cat,
                                                const float* __restrict__ ue,
                                                const float* __restrict__ W,
                                                float* __restrict__ agg,
                                                float* __restrict__ ua,
                                                int n_cat, int n_users, int E, int GA) {
    __shared__ __align__(16) float sw[NREL * D];     // W row-major
    __shared__ float swT[D * NREL];                  // swT[d*32+r] = W[r,d] (user side)
    int warp = threadIdx.x >> 5, lane = threadIdx.x & 31;
    int half = lane >> 4;
    int l16  = lane & 15;

    if ((int)blockIdx.x < GA) {
        // ---------------- head aggregation (online softmax) ----------------
        for (int i = threadIdx.x; i < NREL * D; i += blockDim.x) sw[i] = W[i];
        __syncthreads();
        int strideH = GA * 8;
        for (int h = blockIdx.x * 8 + warp; h < n_cat; h += strideH) {
            int beg = g_off[h], end = g_off[h + 1];
            float4* dst4 = reinterpret_cast<float4*>(agg + (size_t)h * D);
            if (beg == end) {
                if (lane < 16) dst4[lane] = make_float4(0.f, 0.f, 0.f, 0.f);
                continue;
            }
            float m = 0.f, sum = 0.f;                  // att >= 0
            unsigned long long a01 = 0ull, a23 = 0ull;
            for (int b = beg; b < end; b += 32) {
                int i2 = b + lane;
                bool val = i2 < end;
                int2 pa = val ? g_pk2[i2] : make_int2(0, 0);
                float a = val ? __int_as_float(pa.y) : 0.f;
                int mi;
                asm("redux.sync.max.s32 %0, %1, 0xffffffff;" : "=r"(mi) : "r"(__float_as_int(a)));
                float bm = __int_as_float(mi);
                if (b == beg) {
                    m = bm;                            // accs are zero: no rescale needed
                } else {
                    float mnew = fmaxf(m, bm);
                    float scale = __expf(m - mnew);
                    m = mnew;
                    sum *= scale;
                    unsigned long long sc2;
                    PACK2(sc2, scale);
                    MULX2(a01, a01, sc2);
                    MULX2(a23, a23, sc2);
                }
                float e = val ? __expf(a - m) : 0.f;
                float cs = e;
#pragma unroll
                for (int o = 16; o > 0; o >>= 1) cs += __shfl_xor_sync(FULL, cs, o);
                sum += cs;
                int cnt = min(32, end - b);
                int cntUp = (cnt + 7) & ~7;            // pads have e=0, pk=0 -> harmless
                for (int j = 0; j < cntUp; j += 8) {
#pragma unroll
                    for (int q = 0; q < 8; q += 2) {
                        int src = j + q + half;
                        float ej = __shfl_sync(FULL, e, src);
                        int pj = __shfl_sync(FULL, pa.x, src);
                        int tj = pj & 0x1FFFF, rj = pj >> 17;
                        ulonglong2 cv = reinterpret_cast<const ulonglong2*>(cat + (size_t)tj * D)[l16];
                        ulonglong2 wv = reinterpret_cast<const ulonglong2*>(sw + rj * D)[l16];
                        unsigned long long ee, t1;
                        PACK2(ee, ej);
                        MULX2(t1, cv.x, wv.x); FMAX2(a01, t1, ee, a01);
                        MULX2(t1, cv.y, wv.y); FMAX2(a23, t1, ee, a23);
                    }
                }
            }
            float x0, x1, x2, x3;
            UNPK2(x0, x1, a01);
            UNPK2(x2, x3, a23);
            x0 += __shfl_xor_sync(FULL, x0, 16);
            x1 += __shfl_xor_sync(FULL, x1, 16);
            x2 += __shfl_xor_sync(FULL, x2, 16);
            x3 += __shfl_xor_sync(FULL, x3, 16);
            float inv = 1.f / sum;
            if (lane < 16)
                dst4[lane] = make_float4(x0 * inv, x1 * inv, x2 * inv, x3 * inv);
        }
    } else {
        // ---------------- user rows + gating ----------------
        for (int i = threadIdx.x; i < NREL * D; i += blockDim.x) {
            float v = W[i];
            sw[i] = v;
            int r = i / D, d = i % D;
            swT[d * NREL + r] = v;
        }
        __syncthreads();
        int GB = gridDim.x - GA;
        int strideU = GB * 8;
        for (int u = (blockIdx.x - GA) * 8 + warp; u < n_users; u += strideU) {
            int beg = g_off[n_cat + u] - E, end = g_off[n_cat + u + 1] - E;
            unsigned long long a01 = 0ull, a23 = 0ull;
            for (int b = beg; b < end; b += 32) {
                int i2 = b + lane;
                bool val = i2 < end;
                unsigned long long cvp = val ? g_up[i2] : 0ull;
                int c = (int)(unsigned int)cvp;
                float v = val ? __uint_as_float((unsigned int)(cvp >> 32)) : 0.f;
                int cnt = min(32, end - b);
                int cntUp = (cnt + 7) & ~7;
                for (int j = 0; j < cntUp; j += 8) {
#pragma unroll
                    for (int q = 0; q < 8; q += 2) {
                        int src = j + q + half;
                        int cj = __shfl_sync(FULL, c, src);
                        float vj = __shfl_sync(FULL, v, src);
                        ulonglong2 cv = reinterpret_cast<const ulonglong2*>(cat + (size_t)cj * D)[l16];
                        unsigned long long vv;
                        PACK2(vv, vj);
                        FMAX2(a01, cv.x, vv, a01);
                        FMAX2(a23, cv.y, vv, a23);
                    }
                }
            }
            float x0, x1, x2, x3;
            UNPK2(x0, x1, a01);
            UNPK2(x2, x3, a23);
            x0 += __shfl_xor_sync(FULL, x0, 16);
            x1 += __shfl_xor_sync(FULL, x1, 16);
            x2 += __shfl_xor_sync(FULL, x2, 16);
            x3 += __shfl_xor_sync(FULL, x3, 16);
            // redistribute float4@lane<16 -> float2 per lane
            float v0 = __shfl_sync(FULL, x0, lane >> 1);
            float v1 = __shfl_sync(FULL, x1, lane >> 1);
            float v2 = __shfl_sync(FULL, x2, lane >> 1);
            float v3 = __shfl_sync(FULL, x3, lane >> 1);
            float ax = (lane & 1) ? v2 : v0;
            float ay = (lane & 1) ? v3 : v1;
            // gating: score = softmax(ue[u] @ W^T); out = acc * (1 + score @ W)
            float u0 = ue[(size_t)u * D + lane];
            float u1 = ue[(size_t)u * D + 32 + lane];
            float logit = 0.f;
#pragma unroll
            for (int d = 0; d < 32; d++) {
                float ud = __shfl_sync(FULL, u0, d);
                logit += ud * swT[d * NREL + lane];
            }
#pragma unroll
            for (int d = 0; d < 32; d++) {
                float ud = __shfl_sync(FULL, u1, d);
                logit += ud * swT[(d + 32) * NREL + lane];
            }
            float mm = logit;
#pragma unroll
            for (int o = 16; o > 0; o >>= 1) mm = fmaxf(mm, __shfl_xor_sync(FULL, mm, o));
            float p = __expf(logit - mm);
            float s = p;
#pragma unroll
            for (int o = 16; o > 0; o >>= 1) s += __shfl_xor_sync(FULL, s, o);
            p /= s;
            float cx = 0.f, cy = 0.f;
#pragma unroll
            for (int r = 0; r < NREL; r++) {
                float pr = __shfl_sync(FULL, p, r);
                float2 w2 = reinterpret_cast<const float2*>(sw + r * D)[lane];
                cx += pr * w2.x;
                cy += pr * w2.y;
            }
            float2* ud2 = reinterpret_cast<float2*>(ua + (size_t)u * D);
            ud2[lane] = make_float2(ax * (1.f + cx), ay * (1.f + cy));
        }
    }
}

extern "C" void kernel_launch(void* const* d_in, const int* in_sizes, int n_in,
                              void* d_out, int out_size) {
    const float* cat = (const float*)d_in[0];
    const float* ue  = (const float*)d_in[1];
    const int*   ei  = (const int*)d_in[2];
    const int*   et  = (const int*)d_in[3];
    const int*   ir  = (const int*)d_in[4];
    const int*   ic  = (const int*)d_in[5];
    const float* iv  = (const float*)d_in[6];
    const float* W   = (const float*)d_in[7];

    int n_cat   = in_sizes[0] / D;
    int n_users = in_sizes[1] / D;
    int E       = in_sizes[3];
    int nnz     = in_sizes[6];

    const int* head = ei;
    const int* tail = ei + E;

    float* cat_agg  = (float*)d_out;
    float* user_agg = (float*)d_out + (size_t)n_cat * D;

    int n_tot = n_cat + n_users;
    int tot   = E + nnz;
    int nb    = (n_tot + 1023) / 1024;
    int Z     = (n_tot + 256) / 256;
    int SQ    = (n_cat + 255) / 256;

    const int GA = 612, GB = 276;   // GA+GB = 888 = 148 SMs * 6 blocks

    k_front<<<Z + SQ, 256>>>(cat, W, n_cat, n_tot, Z);
    k_hist<<<(tot + 255) / 256, 256>>>(head, ir, E, nnz, n_cat);
    k_scanA<<<nb, 1024>>>(n_tot);
    k_scanB<<<1, 256>>>(nb, n_tot);
    k_scanC<<<nb, 1024>>>(n_tot);
    k_sort<<<(tot + 255) / 256, 256>>>(head, tail, et, ir, ic, iv, E, nnz, n_cat);
    k_big<<<GA + GB, 256>>>(cat, ue, W, cat_agg, user_agg, n_cat, n_users, E, GA);
}